// round 1
// baseline (speedup 1.0000x reference)
#include <cuda_runtime.h>
#include <math.h>

#define E_TOT 262144
#define NN    16384
#define H     256
#define NG    64
#define BVW   260        // padded row width for b_v-augmented (256 + head + tail + pad)
#define KEU   772        // 3H + 4

// ---------------- scratch (device globals; no allocation allowed) ----------------
__device__ float g_be[(size_t)E_TOT * H];      // edge states b_e       (256 MB)
__device__ float g_hidden[(size_t)E_TOT * H];  // eu MLP hidden         (256 MB)
__device__ float g_score[E_TOT];
__device__ float g_ex[E_TOT];
__device__ float g_m[NN];
__device__ float g_s[NN];
__device__ float g_bvaug[(size_t)NN * BVW];    // [b_v | is_head | is_tail | pad]
__device__ float g_gG[NG * 768];
__device__ float g_z[NG];

// ---------------- small elementwise kernels ----------------

__global__ void init_be_kernel(const float* __restrict__ ef, const float* __restrict__ gall) {
    int t = blockIdx.x * 256 + threadIdx.x;      // E*H threads
    int e = t >> 8, j = t & 255;
    g_be[t] = (j < 192) ? ef[(size_t)e * 192 + j] : gall[j - 192];
}

__global__ void init_iter_kernel() {
    int t = blockIdx.x * 256 + threadIdx.x;
    if (t < NN * BVW) g_bvaug[t] = 0.f;
    if (t < NN) { g_m[t] = 0.f; g_s[t] = 0.f; }  // scores are sigmoids > 0, so 0 is a valid -inf
}

__global__ void segmax_kernel(const int* __restrict__ recv) {
    int e = blockIdx.x * 256 + threadIdx.x;
    float sc = g_score[e];
    // positive floats compare correctly as ints
    atomicMax((int*)&g_m[recv[e]], __float_as_int(sc));
}

__global__ void exsum_kernel(const int* __restrict__ recv) {
    int e = blockIdx.x * 256 + threadIdx.x;
    int r = recv[e];
    float ex = expf(g_score[e] - g_m[r]);
    g_ex[e] = ex;
    atomicAdd(&g_s[r], ex);
}

__global__ void scatter_kernel(const int* __restrict__ recv) {
    int t = blockIdx.x * 256 + threadIdx.x;      // E*64 threads, 4 cols each
    int e = t >> 6, c = t & 63;
    int r = recv[e];
    float alpha = g_ex[e] / g_s[r];
    float4 b = *(const float4*)(g_be + (size_t)e * H + c * 4);
    float* dst = g_bvaug + (size_t)r * BVW + c * 4;
    atomicAdd(dst + 0, alpha * b.x);
    atomicAdd(dst + 1, alpha * b.y);
    atomicAdd(dst + 2, alpha * b.z);
    atomicAdd(dst + 3, alpha * b.w);
}

__global__ void finalize_kernel(const int* __restrict__ deg, const int* __restrict__ batch,
                                const int* __restrict__ heads, const int* __restrict__ tails) {
    int t = blockIdx.x * 256 + threadIdx.x;      // N*H threads
    int n = t >> 8, j = t & 255;
    float inv = 1.f / (1.f + (float)deg[n]);
    g_bvaug[(size_t)n * BVW + j] *= inv;
    if (j == 0) {
        int b = batch[n];
        g_bvaug[(size_t)n * BVW + 256] = (heads[b] == n) ? 1.f : 0.f;
        g_bvaug[(size_t)n * BVW + 257] = (tails[b] == n) ? 1.f : 0.f;
    }
}

// ---------------- GEMM kernels: 64x256 block tile, K-tile 32, 8x8 per thread ----------------
// Threads: 256 = (tx 0..31) x (ty 0..7). Thread covers rows ty*8..+8,
// cols {tx*4..+4} and {128+tx*4..+4}. Warp = fixed ty -> A reads broadcast,
// B reads are contiguous float4 -> conflict-free. Warp-shuffle row-reduce in
// fused H->1 epilogues (score, w_e).

#define GEMM_INNER()                                                        \
    _Pragma("unroll")                                                       \
    for (int kk = 0; kk < 32; kk++) {                                       \
        float a[8], b[8];                                                   \
        *(float4*)&a[0] = *(float4*)&As[kk][ty * 8];                        \
        *(float4*)&a[4] = *(float4*)&As[kk][ty * 8 + 4];                    \
        *(float4*)&b[0] = *(float4*)&Bs[kk][tx * 4];                        \
        *(float4*)&b[4] = *(float4*)&Bs[kk][128 + tx * 4];                  \
        _Pragma("unroll")                                                   \
        for (int m = 0; m < 8; m++)                                         \
            _Pragma("unroll")                                               \
            for (int n = 0; n < 8; n++)                                     \
                acc[m][n] = fmaf(a[m], b[n], acc[m][n]);                    \
    }

// score = sigmoid(relu(b_e @ W1 + b1) @ w2 + b2), fully fused
__global__ __launch_bounds__(256) void score_gemm(
    const float* __restrict__ W1, const float* __restrict__ b1,
    const float* __restrict__ w2, const float* __restrict__ b2)
{
    __shared__ float As[32][68];
    __shared__ float Bs[32][256];
    const int tid = threadIdx.x;
    const int tx = tid & 31, ty = tid >> 5;
    const int row0 = blockIdx.x * 64;
    float acc[8][8];
    #pragma unroll
    for (int m = 0; m < 8; m++)
        #pragma unroll
        for (int n = 0; n < 8; n++) acc[m][n] = 0.f;

    for (int kt = 0; kt < H; kt += 32) {
        #pragma unroll
        for (int i = 0; i < 2; i++) {
            int idx = tid + i * 256;
            int r = idx >> 3, k4 = idx & 7;
            float4 a = *(const float4*)(g_be + (size_t)(row0 + r) * H + kt + k4 * 4);
            As[k4 * 4 + 0][r] = a.x; As[k4 * 4 + 1][r] = a.y;
            As[k4 * 4 + 2][r] = a.z; As[k4 * 4 + 3][r] = a.w;
        }
        #pragma unroll
        for (int i = 0; i < 8; i++) {
            int idx = tid + i * 256;
            int k = idx >> 6, n4 = idx & 63;
            *(float4*)&Bs[k][n4 * 4] = *(const float4*)(W1 + (size_t)(kt + k) * H + n4 * 4);
        }
        __syncthreads();
        GEMM_INNER();
        __syncthreads();
    }

    float bb[8], ww[8];
    #pragma unroll
    for (int n = 0; n < 4; n++) {
        bb[n] = b1[tx * 4 + n];           ww[n] = w2[tx * 4 + n];
        bb[n + 4] = b1[128 + tx * 4 + n]; ww[n + 4] = w2[128 + tx * 4 + n];
    }
    float part[8];
    #pragma unroll
    for (int m = 0; m < 8; m++) {
        float s = 0.f;
        #pragma unroll
        for (int n = 0; n < 8; n++) {
            float h = fmaxf(acc[m][n] + bb[n], 0.f);
            s = fmaf(h, ww[n], s);
        }
        part[m] = s;
    }
    #pragma unroll
    for (int off = 16; off > 0; off >>= 1)
        #pragma unroll
        for (int m = 0; m < 8; m++) part[m] += __shfl_xor_sync(0xffffffffu, part[m], off);
    if (tx == 0) {
        float bias2 = b2[0];
        #pragma unroll
        for (int m = 0; m < 8; m++) {
            float x = part[m] + bias2;
            g_score[row0 + ty * 8 + m] = 1.f / (1.f + expf(-x));
        }
    }
}

// hidden = relu([r_v[src] | r_v[recv] | b_e] @ W1 + b1), gather fused into A-tile load
__global__ __launch_bounds__(256) void eu1_gemm(
    const int* __restrict__ src, const int* __restrict__ recv,
    const float* __restrict__ W1, const float* __restrict__ b1)
{
    __shared__ float As[32][68];
    __shared__ float Bs[32][256];
    __shared__ int s_src[64], s_recv[64];
    const int tid = threadIdx.x;
    const int tx = tid & 31, ty = tid >> 5;
    const int row0 = blockIdx.x * 64;
    if (tid < 64) { s_src[tid] = src[row0 + tid]; s_recv[tid] = recv[row0 + tid]; }
    __syncthreads();
    float acc[8][8];
    #pragma unroll
    for (int m = 0; m < 8; m++)
        #pragma unroll
        for (int n = 0; n < 8; n++) acc[m][n] = 0.f;

    for (int kt = 0; kt < KEU; kt += 32) {
        #pragma unroll
        for (int i = 0; i < 8; i++) {
            int idx = tid + i * 256;
            int r = idx >> 5, kk = idx & 31;
            int k = kt + kk;
            float v = 0.f;
            if (k < KEU) {
                if (k < 258)      v = g_bvaug[(size_t)s_src[r] * BVW + k];
                else if (k < 516) v = g_bvaug[(size_t)s_recv[r] * BVW + (k - 258)];
                else              v = g_be[(size_t)(row0 + r) * H + (k - 516)];
            }
            As[kk][r] = v;
        }
        #pragma unroll
        for (int i = 0; i < 8; i++) {
            int idx = tid + i * 256;
            int k = idx >> 6, n4 = idx & 63;
            float4 bv = make_float4(0.f, 0.f, 0.f, 0.f);
            if (kt + k < KEU) bv = *(const float4*)(W1 + (size_t)(kt + k) * H + n4 * 4);
            *(float4*)&Bs[k][n4 * 4] = bv;
        }
        __syncthreads();
        GEMM_INNER();
        __syncthreads();
    }

    float bb[8];
    #pragma unroll
    for (int n = 0; n < 4; n++) { bb[n] = b1[tx * 4 + n]; bb[n + 4] = b1[128 + tx * 4 + n]; }
    #pragma unroll
    for (int m = 0; m < 8; m++) {
        float4 h0 = make_float4(fmaxf(acc[m][0] + bb[0], 0.f), fmaxf(acc[m][1] + bb[1], 0.f),
                                fmaxf(acc[m][2] + bb[2], 0.f), fmaxf(acc[m][3] + bb[3], 0.f));
        float4 h1 = make_float4(fmaxf(acc[m][4] + bb[4], 0.f), fmaxf(acc[m][5] + bb[5], 0.f),
                                fmaxf(acc[m][6] + bb[6], 0.f), fmaxf(acc[m][7] + bb[7], 0.f));
        float* dst = g_hidden + (size_t)(row0 + ty * 8 + m) * H;
        *(float4*)(dst + tx * 4) = h0;
        *(float4*)(dst + 128 + tx * 4) = h1;
    }
}

// b_e = hidden @ W2 + b2; last iter: w_e = sigmoid(b_e @ ew_w + ew_b) fused, b_e store skipped
__global__ __launch_bounds__(256) void eu2_gemm(
    const float* __restrict__ W2, const float* __restrict__ b2,
    float* __restrict__ we_out, const float* __restrict__ eww, const float* __restrict__ ewb)
{
    __shared__ float As[32][68];
    __shared__ float Bs[32][256];
    const int tid = threadIdx.x;
    const int tx = tid & 31, ty = tid >> 5;
    const int row0 = blockIdx.x * 64;
    float acc[8][8];
    #pragma unroll
    for (int m = 0; m < 8; m++)
        #pragma unroll
        for (int n = 0; n < 8; n++) acc[m][n] = 0.f;

    for (int kt = 0; kt < H; kt += 32) {
        #pragma unroll
        for (int i = 0; i < 2; i++) {
            int idx = tid + i * 256;
            int r = idx >> 3, k4 = idx & 7;
            float4 a = *(const float4*)(g_hidden + (size_t)(row0 + r) * H + kt + k4 * 4);
            As[k4 * 4 + 0][r] = a.x; As[k4 * 4 + 1][r] = a.y;
            As[k4 * 4 + 2][r] = a.z; As[k4 * 4 + 3][r] = a.w;
        }
        #pragma unroll
        for (int i = 0; i < 8; i++) {
            int idx = tid + i * 256;
            int k = idx >> 6, n4 = idx & 63;
            *(float4*)&Bs[k][n4 * 4] = *(const float4*)(W2 + (size_t)(kt + k) * H + n4 * 4);
        }
        __syncthreads();
        GEMM_INNER();
        __syncthreads();
    }

    float bb[8];
    #pragma unroll
    for (int n = 0; n < 4; n++) { bb[n] = b2[tx * 4 + n]; bb[n + 4] = b2[128 + tx * 4 + n]; }

    if (we_out == nullptr) {
        #pragma unroll
        for (int m = 0; m < 8; m++) {
            float4 h0 = make_float4(acc[m][0] + bb[0], acc[m][1] + bb[1],
                                    acc[m][2] + bb[2], acc[m][3] + bb[3]);
            float4 h1 = make_float4(acc[m][4] + bb[4], acc[m][5] + bb[5],
                                    acc[m][6] + bb[6], acc[m][7] + bb[7]);
            float* dst = g_be + (size_t)(row0 + ty * 8 + m) * H;
            *(float4*)(dst + tx * 4) = h0;
            *(float4*)(dst + 128 + tx * 4) = h1;
        }
    } else {
        float ww[8];
        #pragma unroll
        for (int n = 0; n < 4; n++) { ww[n] = eww[tx * 4 + n]; ww[n + 4] = eww[128 + tx * 4 + n]; }
        float part[8];
        #pragma unroll
        for (int m = 0; m < 8; m++) {
            float s = 0.f;
            #pragma unroll
            for (int n = 0; n < 8; n++) s = fmaf(acc[m][n] + bb[n], ww[n], s);
            part[m] = s;
        }
        #pragma unroll
        for (int off = 16; off > 0; off >>= 1)
            #pragma unroll
            for (int m = 0; m < 8; m++) part[m] += __shfl_xor_sync(0xffffffffu, part[m], off);
        if (tx == 0) {
            float bias = ewb[0];
            #pragma unroll
            for (int m = 0; m < 8; m++) {
                float x = part[m] + bias;
                we_out[row0 + ty * 8 + m] = 1.f / (1.f + expf(-x));
            }
        }
    }
}

// ---------------- graph readout ----------------

__global__ void gmax_kernel(const int* __restrict__ heads, const int* __restrict__ tails) {
    int g = blockIdx.x, j = threadIdx.x;         // 64 blocks x 256 threads
    float mx = -3.4e38f;
    int base = g * 256;
    for (int n = 0; n < 256; n++)
        mx = fmaxf(mx, g_bvaug[(size_t)(base + n) * BVW + j]);
    g_gG[g * 768 + j]       = mx;
    g_gG[g * 768 + 256 + j] = g_bvaug[(size_t)heads[g] * BVW + j];
    g_gG[g * 768 + 512 + j] = g_bvaug[(size_t)tails[g] * BVW + j];
}

__global__ void gmlp_kernel(const float* __restrict__ W1, const float* __restrict__ b1,
                            const float* __restrict__ w2, const float* __restrict__ b2) {
    __shared__ float row[768];
    __shared__ float red[256];
    int g = blockIdx.x, tid = threadIdx.x;
    for (int i = tid; i < 768; i += 256) row[i] = g_gG[g * 768 + i];
    __syncthreads();
    float h = b1[tid];
    for (int k = 0; k < 768; k++) h = fmaf(row[k], W1[(size_t)k * 256 + tid], h);
    h = fmaxf(h, 0.f);
    red[tid] = h * w2[tid];
    __syncthreads();
    for (int s = 128; s > 0; s >>= 1) {
        if (tid < s) red[tid] += red[tid + s];
        __syncthreads();
    }
    if (tid == 0) g_z[g] = red[0] + b2[0];
}

__global__ void gout_kernel(float* __restrict__ out) {
    __shared__ float zs[NG];
    int tid = threadIdx.x;                       // 768 threads
    if (tid < NG) zs[tid] = g_z[tid];
    __syncthreads();
    float m = -3.4e38f;
    for (int g = 0; g < NG; g++) m = fmaxf(m, zs[g]);
    float denom = 0.f;
    for (int g = 0; g < NG; g++) denom += expf(zs[g] - m);
    float acc = 0.f;
    for (int g = 0; g < NG; g++) acc += (expf(zs[g] - m) / denom) * g_gG[g * 768 + tid];
    out[tid] = acc;
}

// ---------------- launch ----------------

extern "C" void kernel_launch(void* const* d_in, const int* in_sizes, int n_in,
                              void* d_out, int out_size) {
    const float* ef     = (const float*)d_in[0];
    const float* gall   = (const float*)d_in[1];
    const float* ea_w1  = (const float*)d_in[2];
    const float* ea_b1  = (const float*)d_in[3];
    const float* ea_w2  = (const float*)d_in[4];
    const float* ea_b2  = (const float*)d_in[5];
    const float* eu_w1  = (const float*)d_in[6];
    const float* eu_b1  = (const float*)d_in[7];
    const float* eu_w2  = (const float*)d_in[8];
    const float* eu_b2  = (const float*)d_in[9];
    const float* gw_w1  = (const float*)d_in[10];
    const float* gw_b1  = (const float*)d_in[11];
    const float* gw_w2  = (const float*)d_in[12];
    const float* gw_b2  = (const float*)d_in[13];
    const float* ew_w   = (const float*)d_in[14];
    const float* ew_b   = (const float*)d_in[15];
    const int*   eidx   = (const int*)d_in[16];
    const int*   deg    = (const int*)d_in[17];
    const int*   batch  = (const int*)d_in[18];
    const int*   heads  = (const int*)d_in[19];
    const int*   tails  = (const int*)d_in[20];
    const int* src  = eidx;
    const int* recv = eidx + E_TOT;
    float* out = (float*)d_out;

    init_be_kernel<<<E_TOT, 256>>>(ef, gall);    // E*H threads (256 threads/block, E blocks)

    for (int it = 0; it < 3; it++) {
        init_iter_kernel<<<(NN * BVW + 255) / 256, 256>>>();
        score_gemm<<<E_TOT / 64, 256>>>(ea_w1, ea_b1, ea_w2, ea_b2);
        segmax_kernel<<<E_TOT / 256, 256>>>(recv);
        exsum_kernel<<<E_TOT / 256, 256>>>(recv);
        scatter_kernel<<<(E_TOT * 64) / 256, 256>>>(recv);
        finalize_kernel<<<NN, 256>>>(deg, batch, heads, tails);
        eu1_gemm<<<E_TOT / 64, 256>>>(src, recv, eu_w1, eu_b1);
        eu2_gemm<<<E_TOT / 64, 256>>>(eu_w2, eu_b2,
                                      (it == 2) ? out : (float*)nullptr, ew_w, ew_b);
    }

    gmax_kernel<<<NG, 256>>>(heads, tails);
    gmlp_kernel<<<NG, 256>>>(gw_w1, gw_b1, gw_w2, gw_b2);
    gout_kernel<<<1, 768>>>(out + E_TOT);
}